// round 17
// baseline (speedup 1.0000x reference)
#include <cuda_runtime.h>
#include <cuda_fp16.h>
#include <math.h>
#include <stdint.h>

#define Bc 2
#define Lc 2048
#define Dc 1024
#define Hc 16
#define Dhc 64
#define Mtot (Bc*Lc)          // 4096
#define Ntot (Hc*Dhc)         // 1024

typedef __half fp16;

// ------------------------- global scratch (no allocs) -----------------------
__device__ fp16 g_xh[Mtot*Dc], g_xl[Mtot*Dc];       // x hi/lo (A side of QKV)
__device__ fp16 g_Wqh[Dc*Ntot];                     // weights: hi only (B side)
__device__ fp16 g_Wkh[Dc*Ntot];
__device__ fp16 g_Wvh[Dc*Ntot];
__device__ fp16 g_Woh[Dc*Ntot];
__device__ fp16 g_Qh[Bc*Hc*Lc*Dhc], g_Ql[Bc*Hc*Lc*Dhc];   // Q hi/lo (A side of S)
__device__ fp16 g_Kh[Bc*Hc*Lc*Dhc];                       // K hi only (B side)
__device__ fp16 g_Vh[Bc*Hc*Lc*Dhc];                       // V hi only (B side)
__device__ fp16 g_Oh[Mtot*Dc];                            // attn out hi only (A side)

// ------------------------------- helpers ------------------------------------
__device__ __forceinline__ uint32_t smem_u32(const void* p) {
    return (uint32_t)__cvta_generic_to_shared(p);
}
__device__ __forceinline__ void cpa16(void* dst, const void* src) {
    uint32_t d = smem_u32(dst);
    asm volatile("cp.async.cg.shared.global [%0], [%1], 16;\n" :: "r"(d), "l"(src));
}
__device__ __forceinline__ void ldsm4(uint32_t* r, uint32_t a) {
    asm volatile("ldmatrix.sync.aligned.m8n8.x4.shared.b16 {%0,%1,%2,%3}, [%4];\n"
                 : "=r"(r[0]), "=r"(r[1]), "=r"(r[2]), "=r"(r[3]) : "r"(a));
}
__device__ __forceinline__ void ldsm4t(uint32_t* r, uint32_t a) {
    asm volatile("ldmatrix.sync.aligned.m8n8.x4.trans.shared.b16 {%0,%1,%2,%3}, [%4];\n"
                 : "=r"(r[0]), "=r"(r[1]), "=r"(r[2]), "=r"(r[3]) : "r"(a));
}
__device__ __forceinline__ void mma16816(float* c, const uint32_t* a, const uint32_t* b) {
    asm volatile("mma.sync.aligned.m16n8k16.row.col.f32.f16.f16.f32 "
                 "{%0,%1,%2,%3}, {%4,%5,%6,%7}, {%8,%9}, {%0,%1,%2,%3};\n"
                 : "+f"(c[0]), "+f"(c[1]), "+f"(c[2]), "+f"(c[3])
                 : "r"(a[0]), "r"(a[1]), "r"(a[2]), "r"(a[3]), "r"(b[0]), "r"(b[1]));
}
__device__ __forceinline__ void split_pack(float x, float y, uint32_t& hi, uint32_t& lo) {
    __half2 h2 = __floats2half2_rn(x, y);
    float2 hf = __half22float2(h2);
    __half2 l2 = __floats2half2_rn(x - hf.x, y - hf.y);
    hi = *(uint32_t*)&h2; lo = *(uint32_t*)&l2;
}
__device__ __forceinline__ uint32_t pack_h2(float x, float y) {
    __half2 h2 = __floats2half2_rn(x, y);
    return *(uint32_t*)&h2;
}
__device__ __forceinline__ float ex2f(float x) {      // raw MUFU.EX2 (fp32)
    float y;
    asm("ex2.approx.f32 %0, %1;" : "=f"(y) : "f"(x));
    return y;
}

// --------------------------- input prep (one launch) -------------------------
__global__ void prep_kernel(const float4* __restrict__ x,
                            uint2* __restrict__ xh, uint2* __restrict__ xl,
                            const float4* __restrict__ wq, const float4* __restrict__ wk,
                            const float4* __restrict__ wv, const float4* __restrict__ wo,
                            uint2* __restrict__ dq, uint2* __restrict__ dk,
                            uint2* __restrict__ dv, uint2* __restrict__ dwo) {
    int i = blockIdx.x * blockDim.x + threadIdx.x;
    if (blockIdx.y == 0) {
        float4 v = x[i];
        uint2 h, l;
        split_pack(v.x, v.y, h.x, l.x);
        split_pack(v.z, v.w, h.y, l.y);
        xh[i] = h; xl[i] = l;
    } else {
        int w = i >> 18, off = i & 0x3FFFF;          // 262144 float4 per weight
        const float4* s = (w == 0) ? wq : (w == 1) ? wk : (w == 2) ? wv : wo;
        uint2* d = (w == 0) ? dq : (w == 1) ? dk : (w == 2) ? dv : dwo;
        float4 v = s[off];
        uint2 h;
        h.x = pack_h2(v.x, v.y);
        h.y = pack_h2(v.z, v.w);
        d[off] = h;
    }
}

// ------------------------------ GEMM core -----------------------------------
// C[128x128] tile. 256 threads / 8 warps, warp tile 32x64.
// 3-stage cp.async pipeline, single __syncthreads per K-iteration. 2 CTAs/SM.
// LO=true: A = Ah + Al (2-term error-compensated). LO=false: A = Ah only.
#define GEMM_SMEM_BYTES ((3*128*40*2 + 3*32*136) * 2)

template<bool LO>
__device__ __forceinline__ void gemm_mainloop(
    const fp16* __restrict__ Ah, const fp16* __restrict__ Al,
    const fp16* __restrict__ Bh,
    fp16* sAh, fp16* sAl, fp16* sBh,
    int m0, int n0, float acc[2][8][4])
{
    const int tid = threadIdx.x, lane = tid & 31, w = tid >> 5;
    const int wm = w & 3, wn = w >> 2;

#pragma unroll
    for (int mt = 0; mt < 2; mt++)
#pragma unroll
        for (int nt = 0; nt < 8; nt++)
#pragma unroll
            for (int e = 0; e < 4; e++) acc[mt][nt][e] = 0.f;

#define G_LOAD(s, k0g) do{                                                          \
    int r1 = tid >> 2, c1 = (tid & 3) * 8;                                          \
    cpa16(sAh + ((s)*128 + r1)*40 + c1,      Ah + (size_t)(m0 + r1)*Dc + (k0g) + c1);      \
    cpa16(sAh + ((s)*128 + r1 + 64)*40 + c1, Ah + (size_t)(m0 + r1 + 64)*Dc + (k0g) + c1); \
    if (LO) {                                                                       \
        cpa16(sAl + ((s)*128 + r1)*40 + c1,      Al + (size_t)(m0 + r1)*Dc + (k0g) + c1);      \
        cpa16(sAl + ((s)*128 + r1 + 64)*40 + c1, Al + (size_t)(m0 + r1 + 64)*Dc + (k0g) + c1); \
    }                                                                               \
    int r2 = tid >> 4, c2 = (tid & 15) * 8;                                         \
    cpa16(sBh + ((s)*32 + r2)*136 + c2,      Bh + (size_t)((k0g) + r2)*Ntot + n0 + c2);      \
    cpa16(sBh + ((s)*32 + r2 + 16)*136 + c2, Bh + (size_t)((k0g) + r2 + 16)*Ntot + n0 + c2); \
    asm volatile("cp.async.commit_group;\n" ::); } while(0)

    G_LOAD(0, 0);
    G_LOAD(1, 32);
    int s = 0;
    for (int kb = 0; kb < 32; kb++) {
        if (kb < 31) asm volatile("cp.async.wait_group 1;\n" ::: "memory");
        else         asm volatile("cp.async.wait_group 0;\n" ::: "memory");
        __syncthreads();
        if (kb + 2 < 32) {
            int sn = s + 2; if (sn >= 3) sn -= 3;
            G_LOAD(sn, (kb + 2) * 32);
        }
#pragma unroll
        for (int ks = 0; ks < 2; ks++) {
            uint32_t ah[2][4], al[2][4];
#pragma unroll
            for (int mt = 0; mt < 2; mt++) {
                int row = wm * 32 + mt * 16 + (lane & 15);
                int col = ks * 16 + ((lane >> 4) << 3);
                ldsm4(ah[mt], smem_u32(&sAh[(s * 128 + row) * 40 + col]));
                if (LO) ldsm4(al[mt], smem_u32(&sAl[(s * 128 + row) * 40 + col]));
            }
#pragma unroll
            for (int np = 0; np < 4; np++) {
                uint32_t bh[4];
                int rowb = ks * 16 + (lane & 15);
                int colb = wn * 64 + np * 16 + ((lane >> 4) << 3);
                ldsm4t(bh, smem_u32(&sBh[(s * 32 + rowb) * 136 + colb]));
#pragma unroll
                for (int mt = 0; mt < 2; mt++) {
                    mma16816(acc[mt][2*np],     ah[mt], &bh[0]);
                    if (LO) mma16816(acc[mt][2*np], al[mt], &bh[0]);
                    mma16816(acc[mt][2*np + 1], ah[mt], &bh[2]);
                    if (LO) mma16816(acc[mt][2*np + 1], al[mt], &bh[2]);
                }
            }
        }
        if (++s >= 3) s = 0;
    }
#undef G_LOAD
}

// QKV: x @ {Wq,Wk,Wv} -> Q(hi/lo 2-term, pre-scaled by log2e/8) / K(hi) / V(hi)
__global__ __launch_bounds__(256, 2) void gemm_qkv_kernel() {
    extern __shared__ fp16 sm[];
    fp16* sAh = sm;
    fp16* sAl = sAh + 3*128*40;
    fp16* sBh = sAl + 3*128*40;

    const int z = blockIdx.z;
    const fp16* Bh = (z == 0) ? g_Wqh : (z == 1) ? g_Wkh : g_Wvh;
    fp16* Th = (z == 0) ? g_Qh : (z == 1) ? g_Kh : g_Vh;
    // fold 1/sqrt(Dh) * log2(e) into Q so softmax uses pure ex2
    const float sc = (z == 0) ? 0.125f * 1.44269504f : 1.0f;

    const int m0 = blockIdx.y * 128, n0 = blockIdx.x * 128;
    float acc[2][8][4];
    if (z == 0) gemm_mainloop<true >(g_xh, g_xl, Bh, sAh, sAl, sBh, m0, n0, acc);
    else        gemm_mainloop<false>(g_xh, g_xl, Bh, sAh, sAl, sBh, m0, n0, acc);

    const int lane = threadIdx.x & 31, w = threadIdx.x >> 5;
    const int wm = w & 3, wn = w >> 2;
#pragma unroll
    for (int mt = 0; mt < 2; mt++) {
#pragma unroll
        for (int nt = 0; nt < 8; nt++) {
            int m = m0 + wm * 32 + mt * 16 + (lane >> 2);
            int n = n0 + wn * 64 + nt * 8 + ((lane & 3) << 1);
#pragma unroll
            for (int half = 0; half < 2; half++) {
                int mm = m + half * 8;
                int b = mm >> 11, lq = mm & (Lc - 1);
                int h = n >> 6, e = n & (Dhc - 1);
                size_t idx = ((((size_t)b * Hc + h) * Lc) + lq) * Dhc + e;
                float v0 = acc[mt][nt][2*half] * sc;
                float v1 = acc[mt][nt][2*half + 1] * sc;
                if (z == 0) {
                    uint32_t hi, lo;
                    split_pack(v0, v1, hi, lo);
                    *(uint32_t*)&Th[idx] = hi;
                    *(uint32_t*)&g_Ql[idx] = lo;
                } else {
                    *(uint32_t*)&Th[idx] = pack_h2(v0, v1);
                }
            }
        }
    }
}

// proj: g_O(hi) @ Wout(hi) -> out f32
__global__ __launch_bounds__(256, 2) void gemm_proj_kernel(float* __restrict__ out) {
    extern __shared__ fp16 sm[];
    fp16* sAh = sm;
    fp16* sAl = sAh + 3*128*40;
    fp16* sBh = sAl + 3*128*40;

    const int m0 = blockIdx.y * 128, n0 = blockIdx.x * 128;
    float acc[2][8][4];
    gemm_mainloop<false>(g_Oh, (const fp16*)nullptr, g_Woh, sAh, sAl, sBh, m0, n0, acc);

    const int lane = threadIdx.x & 31, w = threadIdx.x >> 5;
    const int wm = w & 3, wn = w >> 2;
#pragma unroll
    for (int mt = 0; mt < 2; mt++) {
#pragma unroll
        for (int nt = 0; nt < 8; nt++) {
            int m = m0 + wm * 32 + mt * 16 + (lane >> 2);
            int n = n0 + wn * 64 + nt * 8 + ((lane & 3) << 1);
            float2 v0 = make_float2(acc[mt][nt][0], acc[mt][nt][1]);
            float2 v1 = make_float2(acc[mt][nt][2], acc[mt][nt][3]);
            *(float2*)&out[(size_t)m * Dc + n]       = v0;
            *(float2*)&out[(size_t)(m + 8) * Dc + n] = v1;
        }
    }
}

// --------------------------- flash attention --------------------------------
// 128 threads / 4 warps per CTA; CTA = one 64-row q tile. 3 CTAs/SM.
// exp2-domain softmax (Q pre-scaled by log2e/8); P fp16 single-term PV.
#define ATTN_SMEM_BYTES ((2*64*72 + 2*3*64*72) * 2)

__global__ __launch_bounds__(128, 3) void attn_kernel() {
    extern __shared__ fp16 sm[];
    fp16* sQh = sm;                  // 64*72
    fp16* sQl = sQh + 64*72;
    fp16* sKh = sQl + 64*72;         // 3 stages * 64*72
    fp16* sVh = sKh + 3*64*72;

    const int tid = threadIdx.x, lane = tid & 31, w = tid >> 5;  // w = 0..3
    const int qt = (int)(gridDim.x - 1 - blockIdx.x);   // heavy tiles first
    const int bh = blockIdx.y;
    const int jmax = qt;
    const size_t base = (size_t)bh * Lc * Dhc;

#define ATT_LOAD(s, j) do{                                                   \
    for (int i = 0; i < 4; i++) {                                            \
        int c = tid + i * 128; int row = c >> 3; int col = (c & 7) * 8;      \
        size_t g = base + ((size_t)(j) * 64 + row) * 64 + col;               \
        size_t so = ((size_t)(s) * 64 + row) * 72 + col;                     \
        cpa16(&sKh[so], &g_Kh[g]);                                           \
        cpa16(&sVh[so], &g_Vh[g]);                                           \
    }                                                                        \
    asm volatile("cp.async.commit_group;\n" ::); } while(0)

    // load 64-row Q tile
    {
        const fp16* Qgh = g_Qh + base + (size_t)qt * 64 * 64;
        const fp16* Qgl = g_Ql + base + (size_t)qt * 64 * 64;
        for (int c = tid; c < 512; c += 128) {
            int row = c >> 3, col = (c & 7) * 8;
            *(uint4*)&sQh[row * 72 + col] = *(const uint4*)&Qgh[row * 64 + col];
            *(uint4*)&sQl[row * 72 + col] = *(const uint4*)&Qgl[row * 64 + col];
        }
    }
    ATT_LOAD(0, 0);
    if (jmax >= 1) ATT_LOAD(1, 1);
    __syncthreads();

    // Q fragments (warp w owns rows w*16 .. w*16+15)
    uint32_t qh[4][4], ql[4][4];
    {
        int row = w * 16 + (lane & 15);
#pragma unroll
        for (int ks = 0; ks < 4; ks++) {
            int col = ks * 16 + ((lane >> 4) << 3);
            ldsm4(qh[ks], smem_u32(&sQh[row * 72 + col]));
            ldsm4(ql[ks], smem_u32(&sQl[row * 72 + col]));
        }
    }

    float m0r = -INFINITY, m1r = -INFINITY, l0 = 0.f, l1 = 0.f;
    float oacc[8][4];
#pragma unroll
    for (int nt = 0; nt < 8; nt++)
#pragma unroll
        for (int e = 0; e < 4; e++) oacc[nt][e] = 0.f;

    int s = 0;
    for (int j = 0; j <= jmax; j++) {
        if (j < jmax) asm volatile("cp.async.wait_group 1;\n" ::: "memory");
        else          asm volatile("cp.async.wait_group 0;\n" ::: "memory");
        __syncthreads();
        if (j + 2 <= jmax) {
            int sn = s + 2; if (sn >= 3) sn -= 3;
            ATT_LOAD(sn, j + 2);
        }

        {
            float sacc[8][4];
#pragma unroll
            for (int nt = 0; nt < 8; nt++)
#pragma unroll
                for (int e = 0; e < 4; e++) sacc[nt][e] = 0.f;

            // S = Q K^T  (log2-domain: Q pre-scaled by log2e/8)
#pragma unroll
            for (int ks = 0; ks < 4; ks++) {
#pragma unroll
                for (int np = 0; np < 4; np++) {
                    uint32_t kh[4];
                    int rown = np * 16 + ((lane >> 4) << 3) + (lane & 7);
                    int coln = ks * 16 + (lane & 8);
                    ldsm4(kh, smem_u32(&sKh[(s * 64 + rown) * 72 + coln]));
                    mma16816(sacc[2*np],     qh[ks], &kh[0]);
                    mma16816(sacc[2*np],     ql[ks], &kh[0]);
                    mma16816(sacc[2*np + 1], qh[ks], &kh[2]);
                    mma16816(sacc[2*np + 1], ql[ks], &kh[2]);
                }
            }

            // causal mask (diagonal tile only)
            const int r0loc = w * 16 + (lane >> 2);
            if (j == qt) {
#pragma unroll
                for (int nt = 0; nt < 8; nt++) {
#pragma unroll
                    for (int e = 0; e < 4; e++) {
                        int c = nt * 8 + ((lane & 3) << 1) + (e & 1);
                        int r = r0loc + ((e >= 2) ? 8 : 0);
                        if (c > r) sacc[nt][e] = -INFINITY;
                    }
                }
            }

            // online softmax (base-2)
            float mx0 = -INFINITY, mx1 = -INFINITY;
#pragma unroll
            for (int nt = 0; nt < 8; nt++) {
                mx0 = fmaxf(mx0, fmaxf(sacc[nt][0], sacc[nt][1]));
                mx1 = fmaxf(mx1, fmaxf(sacc[nt][2], sacc[nt][3]));
            }
            mx0 = fmaxf(mx0, __shfl_xor_sync(0xffffffffu, mx0, 1));
            mx0 = fmaxf(mx0, __shfl_xor_sync(0xffffffffu, mx0, 2));
            mx1 = fmaxf(mx1, __shfl_xor_sync(0xffffffffu, mx1, 1));
            mx1 = fmaxf(mx1, __shfl_xor_sync(0xffffffffu, mx1, 2));

            float mn0 = fmaxf(m0r, mx0), mn1 = fmaxf(m1r, mx1);
            // skip correction ex2 when running max unchanged (saves MUFU)
            float c0 = (mn0 == m0r) ? 1.0f : ex2f(m0r - mn0);
            float c1 = (mn1 == m1r) ? 1.0f : ex2f(m1r - mn1);
            float ps0 = 0.f, ps1 = 0.f;
#pragma unroll
            for (int nt = 0; nt < 8; nt++) {
                sacc[nt][0] = ex2f(sacc[nt][0] - mn0); ps0 += sacc[nt][0];
                sacc[nt][1] = ex2f(sacc[nt][1] - mn0); ps0 += sacc[nt][1];
                sacc[nt][2] = ex2f(sacc[nt][2] - mn1); ps1 += sacc[nt][2];
                sacc[nt][3] = ex2f(sacc[nt][3] - mn1); ps1 += sacc[nt][3];
            }
            ps0 += __shfl_xor_sync(0xffffffffu, ps0, 1);
            ps0 += __shfl_xor_sync(0xffffffffu, ps0, 2);
            ps1 += __shfl_xor_sync(0xffffffffu, ps1, 1);
            ps1 += __shfl_xor_sync(0xffffffffu, ps1, 2);
            l0 = l0 * c0 + ps0; l1 = l1 * c1 + ps1;
            m0r = mn0; m1r = mn1;
#pragma unroll
            for (int nt = 0; nt < 8; nt++) {
                oacc[nt][0] *= c0; oacc[nt][1] *= c0;
                oacc[nt][2] *= c1; oacc[nt][3] *= c1;
            }

            // pack P to fp16 (single-term PV)
            uint32_t ph[4][4];
#pragma unroll
            for (int ks = 0; ks < 4; ks++) {
                int t0 = 2 * ks, t1 = 2 * ks + 1;
                ph[ks][0] = pack_h2(sacc[t0][0], sacc[t0][1]);
                ph[ks][1] = pack_h2(sacc[t0][2], sacc[t0][3]);
                ph[ks][2] = pack_h2(sacc[t1][0], sacc[t1][1]);
                ph[ks][3] = pack_h2(sacc[t1][2], sacc[t1][3]);
            }

            // O += P V
#pragma unroll
            for (int ks = 0; ks < 4; ks++) {
#pragma unroll
                for (int np = 0; np < 4; np++) {
                    uint32_t vh[4];
                    int rowv = ks * 16 + (lane & 15);
                    int colv = np * 16 + ((lane >> 4) << 3);
                    ldsm4t(vh, smem_u32(&sVh[(s * 64 + rowv) * 72 + colv]));
                    mma16816(oacc[2*np],     ph[ks], &vh[0]);
                    mma16816(oacc[2*np + 1], ph[ks], &vh[2]);
                }
            }
        }
        if (++s >= 3) s = 0;
    }

    // epilogue: normalize, store O hi-only as [B*L, 1024]
    const float inv0 = 1.f / l0, inv1 = 1.f / l1;
    const int b = bh >> 4, hh = bh & (Hc - 1);
    const int mrow0 = qt * 64 + w * 16 + (lane >> 2);
#pragma unroll
    for (int nt = 0; nt < 8; nt++) {
        int col = hh * 64 + nt * 8 + ((lane & 3) << 1);
        size_t i0 = ((size_t)b * Lc + mrow0) * Dc + col;
        size_t i1 = ((size_t)b * Lc + mrow0 + 8) * Dc + col;
        *(uint32_t*)&g_Oh[i0] = pack_h2(oacc[nt][0] * inv0, oacc[nt][1] * inv0);
        *(uint32_t*)&g_Oh[i1] = pack_h2(oacc[nt][2] * inv1, oacc[nt][3] * inv1);
    }
#undef ATT_LOAD
}

// ---------------------------------------------------------------------------
extern "C" void kernel_launch(void* const* d_in, const int* in_sizes, int n_in,
                              void* d_out, int out_size)
{
    (void)in_sizes; (void)n_in; (void)out_size;
    const float* x    = (const float*)d_in[0];
    const float* Wq   = (const float*)d_in[1];
    const float* Wk   = (const float*)d_in[2];
    const float* Wv   = (const float*)d_in[3];
    const float* Wout = (const float*)d_in[4];
    float* out = (float*)d_out;

    void *xh, *xl, *wqh, *wkh, *wvh, *woh;
    cudaGetSymbolAddress(&xh,  g_xh);  cudaGetSymbolAddress(&xl, g_xl);
    cudaGetSymbolAddress(&wqh, g_Wqh); cudaGetSymbolAddress(&wkh, g_Wkh);
    cudaGetSymbolAddress(&wvh, g_Wvh); cudaGetSymbolAddress(&woh, g_Woh);

    cudaFuncSetAttribute(gemm_qkv_kernel,
                         cudaFuncAttributeMaxDynamicSharedMemorySize, GEMM_SMEM_BYTES);
    cudaFuncSetAttribute(gemm_proj_kernel,
                         cudaFuncAttributeMaxDynamicSharedMemorySize, GEMM_SMEM_BYTES);
    cudaFuncSetAttribute(attn_kernel,
                         cudaFuncAttributeMaxDynamicSharedMemorySize, ATTN_SMEM_BYTES);

    prep_kernel<<<dim3(Mtot*Dc/4/256, 2), 256>>>(
        (const float4*)x, (uint2*)xh, (uint2*)xl,
        (const float4*)Wq, (const float4*)Wk, (const float4*)Wv, (const float4*)Wout,
        (uint2*)wqh, (uint2*)wkh, (uint2*)wvh, (uint2*)woh);

    gemm_qkv_kernel<<<dim3(Ntot/128, Mtot/128, 3), 256, GEMM_SMEM_BYTES>>>();
    attn_kernel<<<dim3(Lc/64, Bc*Hc), 128, ATTN_SMEM_BYTES>>>();
    gemm_proj_kernel<<<dim3(Dc/128, Mtot/128), 256, GEMM_SMEM_BYTES>>>(out);
}